// round 17
// baseline (speedup 1.0000x reference)
#include <cuda_runtime.h>
#include <math.h>

#define NG    64
#define ATOMS 32
#define NN    2048
#define HID   128
#define FEAT  64

// ---------------- scratch (device globals; no allocations allowed) ----------------
__device__ float d_vals[NN * HID];

__device__ __forceinline__ unsigned f2tf32(float f) {
    unsigned u;
    asm("cvt.rna.tf32.f32 %0, %1;" : "=r"(u) : "f"(f));
    return u;
}

__device__ __forceinline__ void mma_tf32(float c[4], const unsigned a[4],
                                         unsigned b0, unsigned b1) {
    asm volatile(
        "mma.sync.aligned.m16n8k8.row.col.f32.tf32.tf32.f32 "
        "{%0,%1,%2,%3}, {%4,%5,%6,%7}, {%8,%9}, {%0,%1,%2,%3};"
        : "+f"(c[0]), "+f"(c[1]), "+f"(c[2]), "+f"(c[3])
        : "r"(a[0]), "r"(a[1]), "r"(a[2]), "r"(a[3]), "r"(b0), "r"(b1));
}

// ================= K1: per-graph fused emb + x + qkv + attention ================
// 128 blocks (2 per graph, 16 q-rows each), 256 threads.
#define KG_SMEM (28544 * 4)
__global__ void __launch_bounds__(256)
k_graph(const float* __restrict__ h, const float* __restrict__ pos,
        const float* __restrict__ next_type, const int* __restrict__ batch,
        const float* __restrict__ W_emb, const float* __restrict__ Wqkv,
        const float* __restrict__ b_qkv,
        const float* __restrict__ W_g, const float* __restrict__ b_g,
        const float* __restrict__ W_t, const float* __restrict__ b_t) {
    extern __shared__ float sm[];
    float* sW   = sm;
    float* sXt  = sm + 8448;
    float* sX   = sm + 12672;
    float* sQt  = sm + 16768;
    float* sKt  = sm + 18944;
    float* sV   = sm + 23296;
    float* sL   = sm + 27520;
    float* sEmb = sm + 28064;
    float* sNt  = sm + 28192;
    float* sPos = sm + 28256;
    float* sWg  = sm + 28352;
    float* sWt  = sm + 28480;
    float* sGate= sm + 28512;
    float* sIsl = sm + 28528;

    int tid = threadIdx.x;
    int u = blockIdx.x;
    int g = u >> 1, half = u & 1;
    int base = g * ATOMS;
    int rbase = half * 16;
    int warp = tid >> 5, lane = tid & 31;
    int gid = lane >> 2, tig = lane & 3;

    // early prefetch of Wqkv chunk 0 (overlaps with phases A-C)
    float4 wq[8];
#pragma unroll
    for (int v = 0; v < 8; v++) {
        int lin = tid + v * 256;
        int o = lin >> 5, q4 = lin & 31;
        wq[v] = *(const float4*)&Wqkv[o * 128 + q4 * 4];
    }

    // ---- phase A: small inputs + per-graph length ----
    if (tid < FEAT) sNt[tid] = next_type[g * FEAT + tid];
    if (tid < 96) sPos[tid] = pos[base * 3 + tid];
    if (tid < 128) sWg[tid] = W_g[tid];
    if (tid < 32) sWt[tid] = W_t[tid];
    {
        int cnt = 0;
#pragma unroll
        for (int i = tid; i < NN; i += 256) cnt += (batch[i] == g) ? 1 : 0;
#pragma unroll
        for (int o = 16; o; o >>= 1) cnt += __shfl_xor_sync(~0u, cnt, o);
        if (lane == 0) sL[warp] = (float)cnt;
    }
    __syncthreads();

    // ---- phase B: emb + isl ----
    if (tid < HID) {
        const float* w = W_emb + tid * FEAT;
        float acc = 0.f;
#pragma unroll
        for (int f = 0; f < FEAT; f++) acc += sNt[f] * w[f];
        sEmb[tid] = acc;
    }
    if (tid == 0) {
        float s = 0.f;
#pragma unroll
        for (int i = 0; i < 8; i++) s += sL[i];
        sIsl[0] = rsqrtf(s);
    }
    __syncthreads();

    // ---- phase C: x = h * emb (fp32 + tf32) ----
#pragma unroll
    for (int v = 0; v < 4; v++) {
        int lin = tid + v * 256;
        int r = lin >> 5, q4 = lin & 31;
        float4 hv = *(const float4*)&h[(base + r) * HID + q4 * 4];
        float4 ev = *(const float4*)&sEmb[q4 * 4];
        float4 xo;
        xo.x = hv.x * ev.x; xo.y = hv.y * ev.y;
        xo.z = hv.z * ev.z; xo.w = hv.w * ev.w;
        *(float4*)&sX[r * 128 + q4 * 4] = xo;
        uint4 tv;
        tv.x = f2tf32(xo.x); tv.y = f2tf32(xo.y);
        tv.z = f2tf32(xo.z); tv.w = f2tf32(xo.w);
        *(uint4*)&sXt[r * 132 + q4 * 4] = tv;
    }
    __syncthreads();

    // ---- phase D: qkv via 6 W chunks, register-prefetch pipelined ----
    const unsigned* Au = (const unsigned*)sXt;
    for (int ch = 0; ch < 6; ch++) {
        // stage current chunk from regs
#pragma unroll
        for (int v = 0; v < 8; v++) {
            int lin = tid + v * 256;
            int o = lin >> 5, q4 = lin & 31;
            uint4 tv;
            tv.x = f2tf32(wq[v].x); tv.y = f2tf32(wq[v].y);
            tv.z = f2tf32(wq[v].z); tv.w = f2tf32(wq[v].w);
            *(uint4*)&sW[o * 132 + q4 * 4] = tv;
        }
        // prefetch next chunk (latency hides behind MMA)
        if (ch < 5) {
#pragma unroll
            for (int v = 0; v < 8; v++) {
                int lin = tid + v * 256;
                int o = lin >> 5, q4 = lin & 31;
                wq[v] = *(const float4*)&Wqkv[((ch + 1) * 64 + o) * 128 + q4 * 4];
            }
        }
        __syncthreads();
        const unsigned* Wu = (const unsigned*)sW;
        int cb = ch * 64;

        if (ch < 2) {
            float c[4] = {0.f, 0.f, 0.f, 0.f};
            int nb = warp * 8 + gid;
#pragma unroll
            for (int s = 0; s < 16; s++) {
                int kk = s * 8 + tig;
                unsigned a[4];
                a[0] = Au[(rbase + gid) * 132 + kk];
                a[1] = Au[(rbase + gid + 8) * 132 + kk];
                a[2] = Au[(rbase + gid) * 132 + kk + 4];
                a[3] = Au[(rbase + gid + 8) * 132 + kk + 4];
                mma_tf32(c, a, Wu[nb * 132 + kk], Wu[nb * 132 + kk + 4]);
            }
            int lc = cb + warp * 8 + tig * 2;
            float b0 = b_qkv[lc], b1 = b_qkv[lc + 1];
            sQt[lc * 17 + gid]           = c[0] + b0;
            sQt[(lc + 1) * 17 + gid]     = c[1] + b1;
            sQt[lc * 17 + gid + 8]       = c[2] + b0;
            sQt[(lc + 1) * 17 + gid + 8] = c[3] + b1;
        } else {
            int rt = warp >> 2, w4 = warp & 3;
            int r0 = rt * 16 + gid;
            float c[2][4] = {};
#pragma unroll
            for (int s = 0; s < 16; s++) {
                int kk = s * 8 + tig;
                unsigned a[4];
                a[0] = Au[r0 * 132 + kk];
                a[1] = Au[(r0 + 8) * 132 + kk];
                a[2] = Au[r0 * 132 + kk + 4];
                a[3] = Au[(r0 + 8) * 132 + kk + 4];
                int nb0 = w4 * 16 + gid;
                mma_tf32(c[0], a, Wu[nb0 * 132 + kk], Wu[nb0 * 132 + kk + 4]);
                mma_tf32(c[1], a, Wu[(nb0 + 8) * 132 + kk], Wu[(nb0 + 8) * 132 + kk + 4]);
            }
            bool isk = (ch < 4);
            int lcb = (ch & 1) * 64 + w4 * 16;
#pragma unroll
            for (int nt2 = 0; nt2 < 2; nt2++) {
                int lc = lcb + nt2 * 8 + tig * 2;
                int gcol = (isk ? 128 : 256) + lc;
                float b0 = b_qkv[gcol], b1 = b_qkv[gcol + 1];
                if (isk) {
                    sKt[lc * 34 + r0]           = c[nt2][0] + b0;
                    sKt[(lc + 1) * 34 + r0]     = c[nt2][1] + b1;
                    sKt[lc * 34 + r0 + 8]       = c[nt2][2] + b0;
                    sKt[(lc + 1) * 34 + r0 + 8] = c[nt2][3] + b1;
                } else {
                    sV[r0 * 132 + lc]           = c[nt2][0] + b0;
                    sV[r0 * 132 + lc + 1]       = c[nt2][1] + b1;
                    sV[(r0 + 8) * 132 + lc]     = c[nt2][2] + b0;
                    sV[(r0 + 8) * 132 + lc + 1] = c[nt2][3] + b1;
                }
            }
        }
        __syncthreads();
    }

    // ---- phase E: attention ----
    float invs = sIsl[0];
    float bgv = b_g[0];
#pragma unroll
    for (int rr = 0; rr < 2; rr++) {
        int row = warp * 2 + rr;
        const float* xr = sX + (rbase + row) * 128;
        float p = 0.f;
#pragma unroll
        for (int k = lane; k < HID; k += 32) p += xr[k] * sWg[k];
#pragma unroll
        for (int o = 16; o; o >>= 1) p += __shfl_xor_sync(~0u, p, o);
        if (lane == 0) sGate[row] = 1.f / (1.f + __expf(-(p + bgv)));
    }

    {
        int i = tid >> 4;
        int j0 = (tid & 15) * 2;
        float qk0 = 0.f, qk1 = 0.f;
#pragma unroll 8
        for (int k = 0; k < HID; k++) {
            float qa = sQt[k * 17 + i];
            float2 kb = *(const float2*)&sKt[k * 34 + j0];
            qk0 += qa * kb.x;
            qk1 += qa * kb.y;
        }
        float btv = b_t[0];
        int gi = rbase + i;
        float px = sPos[gi * 3 + 0], py = sPos[gi * 3 + 1], pz = sPos[gi * 3 + 2];
        const float step = 10.f / 31.f;
        float qkp[2] = {qk0, qk1};
#pragma unroll
        for (int jj = 0; jj < 2; jj++) {
            int j = j0 + jj;
            float dx = px - sPos[j * 3 + 0];
            float dy = py - sPos[j * 3 + 1];
            float dz = pz - sPos[j * 3 + 2];
            float d = sqrtf(fmaxf(dx * dx + dy * dy + dz * dz, 1e-12f));
            int b0i = __float2int_rn(d * (31.f / 10.f));
            int bs = min(max(b0i - 4, 0), 24);
            float t = btv;
#pragma unroll
            for (int bb = 0; bb < 8; bb++) {
                int b = bs + bb;
                float diff = d - (float)b * step;
                t += __expf(-10.f * diff * diff) * sWt[b];
            }
            sL[i * 34 + j] = qkp[jj] * invs + t;
        }
    }
    __syncthreads();

#pragma unroll
    for (int rr = 0; rr < 2; rr++) {
        int r = warp * 2 + rr;
        float vv = sL[r * 34 + lane];
        float m = vv;
#pragma unroll
        for (int o = 16; o; o >>= 1) m = fmaxf(m, __shfl_xor_sync(~0u, m, o));
        float e = __expf(vv - m);
        float s = e;
#pragma unroll
        for (int o = 16; o; o >>= 1) s += __shfl_xor_sync(~0u, s, o);
        sL[r * 34 + lane] = e / s;
    }
    __syncthreads();

    {
        int rg = tid >> 5, cg = tid & 31;
        int ir = rg * 2, c0 = cg * 4;
        float a00 = 0.f, a01 = 0.f, a02 = 0.f, a03 = 0.f;
        float a10 = 0.f, a11 = 0.f, a12 = 0.f, a13 = 0.f;
#pragma unroll 8
        for (int j = 0; j < 32; j++) {
            float p0 = sL[ir * 34 + j];
            float p1 = sL[(ir + 1) * 34 + j];
            float4 vv = *(const float4*)&sV[j * 132 + c0];
            a00 += p0 * vv.x; a01 += p0 * vv.y; a02 += p0 * vv.z; a03 += p0 * vv.w;
            a10 += p1 * vv.x; a11 += p1 * vv.y; a12 += p1 * vv.z; a13 += p1 * vv.w;
        }
        int grow = base + rbase + ir;
        float gg = sGate[ir];
        float4 xr = *(const float4*)&sX[(rbase + ir) * 128 + c0];
        float4 o;
        o.x = a00 * gg + xr.x; o.y = a01 * gg + xr.y;
        o.z = a02 * gg + xr.z; o.w = a03 * gg + xr.w;
        *(float4*)&d_vals[grow * 128 + c0] = o;
        gg = sGate[ir + 1];
        xr = *(const float4*)&sX[(rbase + ir + 1) * 128 + c0];
        o.x = a10 * gg + xr.x; o.y = a11 * gg + xr.y;
        o.z = a12 * gg + xr.z; o.w = a13 * gg + xr.w;
        *(float4*)&d_vals[(grow + 1) * 128 + c0] = o;
    }
}

// ================= K2: fused dense head, 8 rows/block, grid 256 ================
// Weights streamed per 64-out chunk from original layout, register-prefetched.
// smem floats: sW 0 ([64][132]=8448), sA 8448 ([16][132]), sY0 10560, sY1 12672
#define KH_SMEM (14784 * 4)
__global__ void __launch_bounds__(256)
k_head(const float* __restrict__ Wd0, const float* __restrict__ bd0,
       const float* __restrict__ Wd1, const float* __restrict__ bd1,
       const float* __restrict__ Wd2, const float* __restrict__ bd2,
       float* __restrict__ out) {
    extern __shared__ float sm[];
    float* sW  = sm;
    float* sA  = sm + 8448;
    float* sY0 = sm + 10560;
    float* sY1 = sm + 12672;

    int tid = threadIdx.x;
    int rb = blockIdx.x * 8;
    int warp = tid >> 5, lane = tid & 31;
    int gid = lane >> 2, tig = lane & 3;

    // prefetch L0 chunk 0
    float4 w4[8];
#pragma unroll
    for (int v = 0; v < 8; v++) {
        int lin = tid + v * 256;
        int o = lin >> 5, q4 = lin & 31;
        w4[v] = (o < 106) ? *(const float4*)&Wd0[o * 128 + q4 * 4]
                          : make_float4(0.f, 0.f, 0.f, 0.f);
    }

    // stage A: 8 real rows + 8 zero rows (MMA fragment is 16 rows; upper half discarded)
#pragma unroll
    for (int lin = tid; lin < 512; lin += 256) {
        int r = lin >> 5, q4 = lin & 31;
        uint4 tv = {0u, 0u, 0u, 0u};
        if (r < 8) {
            float4 av = *(const float4*)&d_vals[(rb + r) * 128 + q4 * 4];
            tv.x = f2tf32(av.x); tv.y = f2tf32(av.y);
            tv.z = f2tf32(av.z); tv.w = f2tf32(av.w);
        }
        *(uint4*)&sA[r * 132 + q4 * 4] = tv;
    }

    const unsigned* Wu = (const unsigned*)sW;
    const unsigned* Au = (const unsigned*)sA;
    unsigned* Y0u = (unsigned*)sY0;
    unsigned* Y1u = (unsigned*)sY1;
    float2 w2[14];

    // ---- layer 0: 128 -> 106(pad), SiLU, 2 chunks ----
    for (int ch = 0; ch < 2; ch++) {
#pragma unroll
        for (int v = 0; v < 8; v++) {
            int lin = tid + v * 256;
            int o = lin >> 5, q4 = lin & 31;
            uint4 tv;
            tv.x = f2tf32(w4[v].x); tv.y = f2tf32(w4[v].y);
            tv.z = f2tf32(w4[v].z); tv.w = f2tf32(w4[v].w);
            *(uint4*)&sW[o * 132 + q4 * 4] = tv;
        }
        if (ch == 0) {
            // prefetch L0 chunk 1
#pragma unroll
            for (int v = 0; v < 8; v++) {
                int lin = tid + v * 256;
                int o = lin >> 5, q4 = lin & 31;
                w4[v] = (64 + o < 106) ? *(const float4*)&Wd0[(64 + o) * 128 + q4 * 4]
                                       : make_float4(0.f, 0.f, 0.f, 0.f);
            }
        } else {
            // prefetch L1 chunk 0
#pragma unroll
            for (int v = 0; v < 14; v++) {
                int lin = tid + v * 256;
                int o = lin / 56, p2 = lin - o * 56;
                int k = p2 * 2;
                w2[v] = (o < 85 && k < 106) ? *(const float2*)&Wd1[o * 106 + k]
                                            : make_float2(0.f, 0.f);
            }
        }
        __syncthreads();
        float c[4] = {0.f, 0.f, 0.f, 0.f};
        int nb = warp * 8 + gid;
#pragma unroll
        for (int s = 0; s < 16; s++) {
            int kk = s * 8 + tig;
            unsigned a[4];
            a[0] = Au[gid * 132 + kk];
            a[1] = Au[(gid + 8) * 132 + kk];
            a[2] = Au[gid * 132 + kk + 4];
            a[3] = Au[(gid + 8) * 132 + kk + 4];
            mma_tf32(c, a, Wu[nb * 132 + kk], Wu[nb * 132 + kk + 4]);
        }
        int cg = ch * 64 + warp * 8 + tig * 2;
        float b0 = (cg < 106) ? bd0[cg] : 0.f;
        float b1 = (cg + 1 < 106) ? bd0[cg + 1] : 0.f;
        float z;
        z = c[0] + b0; Y0u[gid * 132 + cg]     = f2tf32(z / (1.f + __expf(-z)));
        z = c[1] + b1; Y0u[gid * 132 + cg + 1] = f2tf32(z / (1.f + __expf(-z)));
        // rows gid+8 discarded (zero-pad region of the fragment)
        __syncthreads();
    }
    // zero Y0 rows 8..15 so layer-1 upper fragment is benign-but-finite
#pragma unroll
    for (int lin = tid; lin < 256; lin += 256) { }
    {
        for (int lin = tid; lin < 8 * 33; lin += 256) {
            int r = 8 + lin / 33, q4 = lin % 33;
            *(uint4*)&Y0u[r * 132 + q4 * 4] = make_uint4(0u, 0u, 0u, 0u);
        }
    }
    __syncthreads();

    // ---- layer 1: 106 -> 85(pad), SiLU, 2 chunks (KSTEPS=14) ----
    float wsc[22];
    for (int ch = 0; ch < 2; ch++) {
#pragma unroll
        for (int v = 0; v < 14; v++) {
            int lin = tid + v * 256;
            int o = lin / 56, p2 = lin - o * 56;
            int k = p2 * 2;
            *(uint2*)&sW[o * 132 + k] = make_uint2(f2tf32(w2[v].x), f2tf32(w2[v].y));
        }
        if (ch == 0) {
            // prefetch L1 chunk 1
#pragma unroll
            for (int v = 0; v < 14; v++) {
                int lin = tid + v * 256;
                int o = lin / 56, p2 = lin - o * 56;
                int k = p2 * 2;
                w2[v] = (64 + o < 85 && k < 106) ? *(const float2*)&Wd1[(64 + o) * 106 + k]
                                                 : make_float2(0.f, 0.f);
            }
        } else {
            // prefetch L2 weights
#pragma unroll
            for (int v = 0; v < 22; v++) {
                int lin = tid + v * 256;
                int o = lin / 88, k = lin - o * 88;
                wsc[v] = (k < 85) ? Wd2[o * 85 + k] : 0.f;
            }
        }
        __syncthreads();
        float c[4] = {0.f, 0.f, 0.f, 0.f};
        int nb = warp * 8 + gid;
#pragma unroll
        for (int s = 0; s < 14; s++) {
            int kk = s * 8 + tig;
            unsigned a[4];
            a[0] = Y0u[gid * 132 + kk];
            a[1] = Y0u[(gid + 8) * 132 + kk];
            a[2] = Y0u[gid * 132 + kk + 4];
            a[3] = Y0u[(gid + 8) * 132 + kk + 4];
            mma_tf32(c, a, Wu[nb * 132 + kk], Wu[nb * 132 + kk + 4]);
        }
        int cg = ch * 64 + warp * 8 + tig * 2;
        float b0 = (cg < 85) ? bd1[cg] : 0.f;
        float b1 = (cg + 1 < 85) ? bd1[cg + 1] : 0.f;
        float z;
        z = c[0] + b0; Y1u[gid * 132 + cg]     = f2tf32(z / (1.f + __expf(-z)));
        z = c[1] + b1; Y1u[gid * 132 + cg + 1] = f2tf32(z / (1.f + __expf(-z)));
        __syncthreads();
    }

    // ---- layer 2: 85 -> 64, linear (KSTEPS=11), then log_softmax ----
    float c2[4] = {0.f, 0.f, 0.f, 0.f};
    {
#pragma unroll
        for (int v = 0; v < 22; v++) {
            int lin = tid + v * 256;
            int o = lin / 88, k = lin - o * 88;
            sW[o * 132 + k] = __uint_as_float(f2tf32(wsc[v]));
        }
        __syncthreads();
        int nb = warp * 8 + gid;
#pragma unroll
        for (int s = 0; s < 11; s++) {
            int kk = s * 8 + tig;
            unsigned a[4];
            a[0] = Y1u[gid * 132 + kk];
            a[1] = Y1u[(gid + 8) * 132 + kk];
            a[2] = Y1u[gid * 132 + kk + 4];
            a[3] = Y1u[(gid + 8) * 132 + kk + 4];
            mma_tf32(c2, a, Wu[nb * 132 + kk], Wu[nb * 132 + kk + 4]);
        }
    }
    __syncthreads();   // done reading sW; reuse as sY[8][66]

    float* sY = sW;
    {
        int lc = warp * 8 + tig * 2;
        float b0 = bd2[lc], b1 = bd2[lc + 1];
        sY[gid * 66 + lc]     = c2[0] + b0;
        sY[gid * 66 + lc + 1] = c2[1] + b1;
    }
    __syncthreads();

    // log_softmax: warp w -> row w (8 rows)
    {
        int r = warp;
        float v0 = sY[r * 66 + lane];
        float v1 = sY[r * 66 + 32 + lane];
        float m = fmaxf(v0, v1);
#pragma unroll
        for (int o = 16; o; o >>= 1) m = fmaxf(m, __shfl_xor_sync(~0u, m, o));
        float s = __expf(v0 - m) + __expf(v1 - m);
#pragma unroll
        for (int o = 16; o; o >>= 1) s += __shfl_xor_sync(~0u, s, o);
        float ls = logf(s) + m;
        out[(rb + r) * 64 + lane] = v0 - ls;
        out[(rb + r) * 64 + 32 + lane] = v1 - ls;
    }
}

// ---------------- launch ----------------
extern "C" void kernel_launch(void* const* d_in, const int* in_sizes, int n_in,
                              void* d_out, int out_size) {
    const float* h     = (const float*)d_in[0];
    const float* pos   = (const float*)d_in[1];
    const float* nt    = (const float*)d_in[2];
    const int*   batch = (const int*)d_in[3];
    const float* W_emb = (const float*)d_in[4];
    const float* W_qkv = (const float*)d_in[5];
    const float* b_qkv = (const float*)d_in[6];
    // d_in[7]=W_b, d_in[8]=b_b : per-row bias, drops out of softmax
    const float* W_g   = (const float*)d_in[9];
    const float* b_g   = (const float*)d_in[10];
    const float* W_t   = (const float*)d_in[11];
    const float* b_t   = (const float*)d_in[12];
    const float* W_d0  = (const float*)d_in[13];
    const float* b_d0  = (const float*)d_in[14];
    const float* W_d1  = (const float*)d_in[15];
    const float* b_d1  = (const float*)d_in[16];
    const float* W_d2  = (const float*)d_in[17];
    const float* b_d2  = (const float*)d_in[18];
    float* out = (float*)d_out;

    cudaFuncSetAttribute(k_graph, cudaFuncAttributeMaxDynamicSharedMemorySize, KG_SMEM);
    cudaFuncSetAttribute(k_head, cudaFuncAttributeMaxDynamicSharedMemorySize, KH_SMEM);

    k_graph<<<128, 256, KG_SMEM>>>(h, pos, nt, batch, W_emb, W_qkv, b_qkv,
                                   W_g, b_g, W_t, b_t);
    k_head<<<256, 256, KH_SMEM>>>(W_d0, b_d0, W_d1, b_d1, W_d2, b_d2, out);
}